// round 2
// baseline (speedup 1.0000x reference)
#include <cuda_runtime.h>

typedef unsigned long long u64;

// ---------------- static scratch (no allocations allowed) ----------------
// y1 raw / normalized (in-place), y2 raw, parity-effective conv1 weights, stats
__device__ float g_y1[4 * 32768 * 128];          // 67 MB
__device__ float g_y2[4 * 32768 * 128];          // 67 MB
__device__ float g_w1e[4 * 8 * 8 * 256 * 128];   // 33.5 MB  [b][parity][tap][cin][cout]
__device__ float g_sum[512];
__device__ float g_sq[512];
__device__ float g_scale[512];
__device__ float g_bias[512];

// ---------------- packed fp32x2 helpers ----------------
__device__ __forceinline__ u64 pk2(float lo, float hi) {
    u64 r; asm("mov.b64 %0, {%1,%2};" : "=l"(r) : "f"(lo), "f"(hi)); return r;
}
__device__ __forceinline__ void ffma2(u64& a, u64 x, u64 y) {
    asm("fma.rn.f32x2 %0, %1, %2, %0;" : "+l"(a) : "l"(x), "l"(y));
}
__device__ __forceinline__ float lo32(u64 v) { return __int_as_float((int)(unsigned)v); }
__device__ __forceinline__ float hi32(u64 v) { return __int_as_float((int)(v >> 32)); }

// ---------------- stats ----------------
__global__ void zero_stats_kernel() {
    int t = threadIdx.x;  // launched with 512 threads
    g_sum[t] = 0.f; g_sq[t] = 0.f;
}

__global__ void finalize_stats_kernel() {
    int t = threadIdx.x;  // 512 threads
    const float inv = 1.f / 32768.f;
    float m = g_sum[t] * inv;
    float v = g_sq[t] * inv - m * m;
    float sc = rsqrtf(v + 1e-5f);
    g_scale[t] = sc;
    g_bias[t]  = -m * sc;
}

// ---------------- conv1 parity-collapsed weights ----------------
// Upsample(2x, nearest) then 3-tap SAME conv == per output-parity 2-tap conv
// on the 16-grid. Per dim: p==0: tap0<-{k0}, tap1<-{k1+k2}; p==1: tap0<-{k0+k1}, tap1<-{k2}.
__global__ void prep_w1e_kernel(const float* __restrict__ w1) {
    int i = blockIdx.x * 256 + threadIdx.x;   // 8,388,608 total
    int cout = i & 127;
    int cin  = (i >> 7) & 255;
    int tap  = (i >> 15) & 7;
    int par  = (i >> 18) & 7;
    int b    = i >> 21;
    int pd = (par >> 2) & 1, ph = (par >> 1) & 1, pw = par & 1;
    int td = (tap >> 2) & 1, th = (tap >> 1) & 1, tw = tap & 1;

    int sd = (pd == 0) ? (td == 0 ? 0 : 1) : (td == 0 ? 0 : 2);
    int nd = (pd == 0) ? (td == 0 ? 1 : 2) : (td == 0 ? 2 : 1);
    int sh = (ph == 0) ? (th == 0 ? 0 : 1) : (th == 0 ? 0 : 2);
    int nh = (ph == 0) ? (th == 0 ? 1 : 2) : (th == 0 ? 2 : 1);
    int sw = (pw == 0) ? (tw == 0 ? 0 : 1) : (tw == 0 ? 0 : 2);
    int nw = (pw == 0) ? (tw == 0 ? 1 : 2) : (tw == 0 ? 2 : 1);

    float s = 0.f;
    for (int a = 0; a < nd; a++)
        for (int e = 0; e < nh; e++)
            for (int f = 0; f < nw; f++) {
                int kd = sd + a, kh = sh + e, kw = sw + f;
                s += w1[((size_t)(((b * 3 + kd) * 3 + kh) * 3 + kw) * 256 + cin) * 128 + cout];
            }
    g_w1e[i] = s;
}

// ---------------- implicit-GEMM conv ----------------
// Block: 64 spatial (4x4x4) x 128 cout, 256 threads.
// Thread: 4 M x 8 cout (4 f32x2 pairs). K chunks of 16.
// MODE 0: conv1 (parity form): gather x[16^3,256], W=g_w1e, out=g_y1 (raw).
// MODE 1: conv2: gather concat(g_y1 normed, skip)[32^3,256], W=w2, out=g_y2.
template <int MODE>
__global__ void __launch_bounds__(256, 2)
conv_kernel(const float* __restrict__ ext0, const float* __restrict__ ext1) {
    // 16-byte alignment REQUIRED: mainloop uses LDS.128 / STS.128 on these.
    __shared__ __align__(16) u64 As[16][66];   // [kk][m], value duplicated (row = 528B, mult of 16)
    __shared__ __align__(16) u64 Bs[16][64];   // [kk][cout-pair] (row = 512B)

    const float* inA = (MODE == 0) ? ext0 : g_y1;   // x  | normed y1
    const float* inB = ext0;                        // -  | skip
    const float* W   = (MODE == 0) ? g_w1e : ext1;  // w1e| w2
    float* out       = (MODE == 0) ? g_y1 : g_y2;

    const int t    = threadIdx.x;
    const int bx   = blockIdx.x;
    const int b    = bx >> 9;
    const int tile = bx & 511;

    // loader role: 16 consecutive channels (kk) coalesced per 16 threads
    const int kkL = t & 15;
    const int mL  = t >> 4;
    // compute role
    const int ng = t & 15;
    const int m0 = (t >> 4) << 2;
    const int p0 = ng << 2;

    int oz0, oy0, ox0, pd = 0, ph = 0, pw = 0, par = 0;
    if (MODE == 0) {
        par = tile >> 6;
        pd = (par >> 2) & 1; ph = (par >> 1) & 1; pw = par & 1;
        int sub = tile & 63;
        oz0 = (sub >> 4) << 2; oy0 = ((sub >> 2) & 3) << 2; ox0 = (sub & 3) << 2;
    } else {
        oz0 = (tile >> 6) << 2; oy0 = ((tile >> 3) & 7) << 2; ox0 = (tile & 7) << 2;
    }

    // loader base coords for its 4 m values
    int gz[4], gy[4], gx[4];
#pragma unroll
    for (int r = 0; r < 4; ++r) {
        int m = mL + (r << 4);
        gz[r] = oz0 + (m >> 4);
        gy[r] = oy0 + ((m >> 2) & 3);
        gx[r] = ox0 + (m & 3);
    }

    u64 acc[4][4];
#pragma unroll
    for (int i = 0; i < 4; i++)
#pragma unroll
        for (int j = 0; j < 4; j++) acc[i][j] = 0ULL;

    const int NTAPS = (MODE == 0) ? 8 : 27;

    for (int tap = 0; tap < NTAPS; ++tap) {
        int base[4]; bool val[4];
        if (MODE == 0) {
            int td = (tap >> 2) & 1, th = (tap >> 1) & 1, tw = tap & 1;
#pragma unroll
            for (int r = 0; r < 4; ++r) {
                int z = gz[r] + td + pd - 1;
                int y = gy[r] + th + ph - 1;
                int x = gx[r] + tw + pw - 1;
                val[r] = ((unsigned)z < 16u) && ((unsigned)y < 16u) && ((unsigned)x < 16u);
                base[r] = (((b * 16 + z) * 16 + y) * 16 + x) * 256;
            }
        } else {
            int kd = tap / 9, kh = (tap / 3) % 3, kw = tap % 3;
#pragma unroll
            for (int r = 0; r < 4; ++r) {
                int z = gz[r] + kd - 1;
                int y = gy[r] + kh - 1;
                int x = gx[r] + kw - 1;
                val[r] = ((unsigned)z < 32u) && ((unsigned)y < 32u) && ((unsigned)x < 32u);
                base[r] = (((b * 32 + z) * 32 + y) * 32 + x) * 128;
            }
        }
        const float* Wt = W + (size_t)((MODE == 0) ? ((b * 8 + par) * 8 + tap)
                                                   : (b * 27 + tap)) * (256 * 128);

        for (int cc = 0; cc < 16; ++cc) {
            const int c0 = cc << 4;
            __syncthreads();
            // --- stage A (gathered input, duplicated into f32x2) ---
#pragma unroll
            for (int r = 0; r < 4; ++r) {
                float v = 0.f;
                if (val[r]) {
                    if (MODE == 0) {
                        v = inA[base[r] + c0 + kkL];
                    } else {
                        int c = c0 + kkL;
                        v = (c0 < 128) ? inA[base[r] + c] : inB[base[r] + c - 128];
                    }
                }
                As[kkL][mL + (r << 4)] = pk2(v, v);
            }
            // --- stage B (weights, contiguous 8KB chunk) ---
            {
                const float4* src = (const float4*)(Wt + (c0 << 7));
                float4* dstv = (float4*)(&Bs[0][0]);
                dstv[t]       = src[t];
                dstv[t + 256] = src[t + 256];
            }
            __syncthreads();
            // --- FFMA2 mainloop: 4 LDS.128 + 16 FFMA2 per kk ---
#pragma unroll
            for (int kk = 0; kk < 16; ++kk) {
                ulonglong2 A01 = *(const ulonglong2*)&As[kk][m0];
                ulonglong2 A23 = *(const ulonglong2*)&As[kk][m0 + 2];
                ulonglong2 B01 = *(const ulonglong2*)&Bs[kk][p0];
                ulonglong2 B23 = *(const ulonglong2*)&Bs[kk][p0 + 2];
                ffma2(acc[0][0], A01.x, B01.x); ffma2(acc[0][1], A01.x, B01.y);
                ffma2(acc[0][2], A01.x, B23.x); ffma2(acc[0][3], A01.x, B23.y);
                ffma2(acc[1][0], A01.y, B01.x); ffma2(acc[1][1], A01.y, B01.y);
                ffma2(acc[1][2], A01.y, B23.x); ffma2(acc[1][3], A01.y, B23.y);
                ffma2(acc[2][0], A23.x, B01.x); ffma2(acc[2][1], A23.x, B01.y);
                ffma2(acc[2][2], A23.x, B23.x); ffma2(acc[2][3], A23.x, B23.y);
                ffma2(acc[3][0], A23.y, B01.x); ffma2(acc[3][1], A23.y, B01.y);
                ffma2(acc[3][2], A23.y, B23.x); ffma2(acc[3][3], A23.y, B23.y);
            }
        }
    }

    // ---- epilogue: raw conv output (norm applied later) ----
#pragma unroll
    for (int i = 0; i < 4; i++) {
        int m = m0 + i;
        int lz = m >> 4, ly = (m >> 2) & 3, lx = m & 3;
        int oidx;
        if (MODE == 0) {
            int oz = ((oz0 + lz) << 1) + pd;
            int oy = ((oy0 + ly) << 1) + ph;
            int ox = ((ox0 + lx) << 1) + pw;
            oidx = (((b * 32 + oz) * 32 + oy) * 32 + ox) * 128 + (ng << 3);
        } else {
            oidx = (((b * 32 + (oz0 + lz)) * 32 + (oy0 + ly)) * 32 + (ox0 + lx)) * 128 + (ng << 3);
        }
        float4 v0 = make_float4(lo32(acc[i][0]), hi32(acc[i][0]), lo32(acc[i][1]), hi32(acc[i][1]));
        float4 v1 = make_float4(lo32(acc[i][2]), hi32(acc[i][2]), lo32(acc[i][3]), hi32(acc[i][3]));
        *(float4*)(out + oidx)     = v0;
        *(float4*)(out + oidx + 4) = v1;
    }
}

// ---------------- instance-norm reduction ----------------
template <int SRC>  // 0 -> g_y1, 1 -> g_y2
__global__ void reduce_stats_kernel() {
    const float* y = (SRC == 0) ? g_y1 : g_y2;
    int b = blockIdx.x >> 5;
    int chunk = blockIdx.x & 31;
    int c = threadIdx.x & 127;
    int h = threadIdx.x >> 7;
    const float* p = y + ((size_t)(b * 32768 + chunk * 1024 + h * 512)) * 128 + c;
    float s0 = 0.f, s1 = 0.f, q0 = 0.f, q1 = 0.f;
#pragma unroll 4
    for (int i = 0; i < 512; i += 2) {
        float v0 = p[(size_t)i * 128];
        float v1 = p[(size_t)(i + 1) * 128];
        s0 += v0; q0 += v0 * v0;
        s1 += v1; q1 += v1 * v1;
    }
    __shared__ float S[256], Q[256];
    S[threadIdx.x] = s0 + s1;
    Q[threadIdx.x] = q0 + q1;
    __syncthreads();
    if (h == 0) {
        atomicAdd(&g_sum[b * 128 + c], S[c] + S[c + 128]);
        atomicAdd(&g_sq[b * 128 + c],  Q[c] + Q[c + 128]);
    }
}

// ---------------- fused normalize + relu ----------------
template <int SRC>  // 0: g_y1 -> g_y1 (in place); 1: g_y2 -> dst
__global__ void norm_relu_kernel(float* __restrict__ dst_param) {
    const float* src = (SRC == 0) ? g_y1 : g_y2;
    float* dst       = (SRC == 0) ? g_y1 : dst_param;
    int i4 = blockIdx.x * 256 + threadIdx.x;    // 4,194,304 float4s
    size_t i = (size_t)i4 * 4;
    int c = (int)(i & 127);
    int b = (int)(i >> 22);
    int bc = b * 128 + c;
    float4 v = *(const float4*)(src + i);
    v.x = fmaxf(fmaf(v.x, g_scale[bc],     g_bias[bc]),     0.f);
    v.y = fmaxf(fmaf(v.y, g_scale[bc + 1], g_bias[bc + 1]), 0.f);
    v.z = fmaxf(fmaf(v.z, g_scale[bc + 2], g_bias[bc + 2]), 0.f);
    v.w = fmaxf(fmaf(v.w, g_scale[bc + 3], g_bias[bc + 3]), 0.f);
    *(float4*)(dst + i) = v;
}

// ---------------- launch ----------------
extern "C" void kernel_launch(void* const* d_in, const int* in_sizes, int n_in,
                              void* d_out, int out_size) {
    const float* x    = (const float*)d_in[0];  // [4,16,16,16,256]
    const float* w1   = (const float*)d_in[1];  // [4,3,3,3,256,128]
    const float* w2   = (const float*)d_in[2];  // [4,3,3,3,256,128]
    const float* skip = (const float*)d_in[3];  // [4,32,32,32,128]
    float* out = (float*)d_out;                 // [4,32,32,32,128]
    (void)in_sizes; (void)n_in; (void)out_size;

    // stage 1: upsample+conv1 (parity-collapsed) -> IN -> relu
    zero_stats_kernel<<<1, 512>>>();
    prep_w1e_kernel<<<32768, 256>>>(w1);
    conv_kernel<0><<<2048, 256>>>(x, nullptr);
    reduce_stats_kernel<0><<<128, 256>>>();
    finalize_stats_kernel<<<1, 512>>>();
    norm_relu_kernel<0><<<16384, 256>>>(nullptr);

    // stage 2: concat(y1n, skip) -> conv2 -> IN -> relu
    zero_stats_kernel<<<1, 512>>>();
    conv_kernel<1><<<2048, 256>>>(skip, w2);
    reduce_stats_kernel<1><<<128, 256>>>();
    finalize_stats_kernel<<<1, 512>>>();
    norm_relu_kernel<1><<<16384, 256>>>(out);
}

// round 4
// speedup vs baseline: 1.4952x; 1.4952x over previous
#include <cuda_runtime.h>

typedef unsigned long long u64;

// ---------------- static scratch (no allocations allowed) ----------------
__device__ float g_y1[4 * 32768 * 128];          // 67 MB
__device__ float g_y2[4 * 32768 * 128];          // 67 MB
__device__ float g_w1e[4 * 8 * 8 * 256 * 128];   // 33.5 MB  [b][parity][tap][cin][cout]
__device__ float g_sum[512];
__device__ float g_sq[512];
__device__ float g_scale[512];
__device__ float g_bias[512];

// ---------------- packed fp32x2 helpers ----------------
__device__ __forceinline__ u64 pk2(float lo, float hi) {
    u64 r; asm("mov.b64 %0, {%1,%2};" : "=l"(r) : "f"(lo), "f"(hi)); return r;
}
__device__ __forceinline__ void ffma2(u64& a, u64 x, u64 y) {
    asm("fma.rn.f32x2 %0, %1, %2, %0;" : "+l"(a) : "l"(x), "l"(y));
}
__device__ __forceinline__ float lo32(u64 v) { return __int_as_float((int)(unsigned)v); }
__device__ __forceinline__ float hi32(u64 v) { return __int_as_float((int)(v >> 32)); }

__device__ __forceinline__ void cpasync16(void* dst_smem, const void* src) {
    unsigned sa = (unsigned)__cvta_generic_to_shared(dst_smem);
    asm volatile("cp.async.cg.shared.global [%0], [%1], 16;\n" :: "r"(sa), "l"(src));
}

// ---------------- stats ----------------
__global__ void zero_stats_kernel() {
    int t = threadIdx.x;  // 512 threads
    g_sum[t] = 0.f; g_sq[t] = 0.f;
}

__global__ void finalize_stats_kernel() {
    int t = threadIdx.x;  // 512 threads
    const float inv = 1.f / 32768.f;
    float m = g_sum[t] * inv;
    float v = g_sq[t] * inv - m * m;
    float sc = rsqrtf(v + 1e-5f);
    g_scale[t] = sc;
    g_bias[t]  = -m * sc;
}

// ---------------- conv1 parity-collapsed weights ----------------
// Upsample(2x nearest) + 3-tap SAME conv == per-output-parity 2-tap conv on 16-grid.
__global__ void prep_w1e_kernel(const float* __restrict__ w1) {
    int i = blockIdx.x * 256 + threadIdx.x;   // 8,388,608 total
    int cout = i & 127;
    int cin  = (i >> 7) & 255;
    int tap  = (i >> 15) & 7;
    int par  = (i >> 18) & 7;
    int b    = i >> 21;
    int pd = (par >> 2) & 1, ph = (par >> 1) & 1, pw = par & 1;
    int td = (tap >> 2) & 1, th = (tap >> 1) & 1, tw = tap & 1;

    int sd = (pd == 0) ? (td == 0 ? 0 : 1) : (td == 0 ? 0 : 2);
    int nd = (pd == 0) ? (td == 0 ? 1 : 2) : (td == 0 ? 2 : 1);
    int sh = (ph == 0) ? (th == 0 ? 0 : 1) : (th == 0 ? 0 : 2);
    int nh = (ph == 0) ? (th == 0 ? 1 : 2) : (th == 0 ? 2 : 1);
    int sw = (pw == 0) ? (tw == 0 ? 0 : 1) : (tw == 0 ? 0 : 2);
    int nw = (pw == 0) ? (tw == 0 ? 1 : 2) : (tw == 0 ? 2 : 1);

    float s = 0.f;
    for (int a = 0; a < nd; a++)
        for (int e = 0; e < nh; e++)
            for (int f = 0; f < nw; f++) {
                int kd = sd + a, kh = sh + e, kw = sw + f;
                s += w1[((size_t)(((b * 3 + kd) * 3 + kh) * 3 + kw) * 256 + cin) * 128 + cout];
            }
    g_w1e[i] = s;
}

// ---------------- pipelined implicit-GEMM conv ----------------
// Block: 64 spatial (4x4x4) x 128 cout, 256 threads. Thread: 4 M x 8 cout.
// K pipeline: chunk=16 cin; B via cp.async (4-deep ring), A via LDG->reg->STS (2-deep).
// One __syncthreads per chunk.
template <int MODE>
__global__ void __launch_bounds__(256, 2)
conv_kernel(const float* __restrict__ ext0, const float* __restrict__ ext1) {
    __shared__ __align__(16) u64 As[2][16][64];   // 16 KB  [buf][kk][m] (duplicated f32x2)
    __shared__ __align__(16) u64 Bs[4][16][64];   // 32 KB  [buf][kk][cout-pair]

    const float* inA = (MODE == 0) ? ext0 : g_y1;   // x  | normed y1
    const float* inB = ext0;                        // -  | skip
    const float* W   = (MODE == 0) ? g_w1e : ext1;  // w1e| w2
    float* out       = (MODE == 0) ? g_y1 : g_y2;

    const int t    = threadIdx.x;
    const int bx   = blockIdx.x;
    const int b    = bx >> 9;
    const int tile = bx & 511;

    // staging role: thread -> (one m, 4 consecutive kk)
    const int mS = t & 63;
    const int kg = t >> 6;          // kk group: kk = 4*kg + j
    // compute role
    const int ng = t & 15;          // owns cout-pairs {ng, ng+16, ng+32, ng+48}
    const int m0 = (t >> 4) << 2;

    int oz0, oy0, ox0, pd = 0, ph = 0, pw = 0, par = 0;
    if (MODE == 0) {
        par = tile >> 6;
        pd = (par >> 2) & 1; ph = (par >> 1) & 1; pw = par & 1;
        int sub = tile & 63;
        oz0 = (sub >> 4) << 2; oy0 = ((sub >> 2) & 3) << 2; ox0 = (sub & 3) << 2;
    } else {
        oz0 = (tile >> 6) << 2; oy0 = ((tile >> 3) & 7) << 2; ox0 = (tile & 7) << 2;
    }

    // staging coords for this thread's m
    const int sz = oz0 + (mS >> 4);
    const int sy = oy0 + ((mS >> 2) & 3);
    const int sx = ox0 + (mS & 3);

    const int NTAPS  = (MODE == 0) ? 8 : 27;
    const int NCHUNK = NTAPS * 16;

    // ---- helpers ----
    auto ld_a = [&](int idx) -> float4 {
        int tap = idx >> 4;
        int c0  = (idx & 15) << 4;
        float4 r = make_float4(0.f, 0.f, 0.f, 0.f);
        if (MODE == 0) {
            int td = (tap >> 2) & 1, th = (tap >> 1) & 1, tw = tap & 1;
            int z = sz + td + pd - 1, y = sy + th + ph - 1, x = sx + tw + pw - 1;
            if (((unsigned)z < 16u) && ((unsigned)y < 16u) && ((unsigned)x < 16u)) {
                size_t off = ((size_t)(((b * 16 + z) * 16 + y) * 16 + x)) * 256 + c0 + (kg << 2);
                r = *(const float4*)(inA + off);
            }
        } else {
            int kd = tap / 9, kh = (tap / 3) % 3, kw = tap % 3;
            int z = sz + kd - 1, y = sy + kh - 1, x = sx + kw - 1;
            if (((unsigned)z < 32u) && ((unsigned)y < 32u) && ((unsigned)x < 32u)) {
                size_t base = ((size_t)(((b * 32 + z) * 32 + y) * 32 + x)) * 128;
                int c = c0 + (kg << 2);
                const float* p = (c < 128) ? (inA + base + c) : (inB + base + c - 128);
                r = *(const float4*)p;
            }
        }
        return r;
    };
    auto stage_b = [&](int idx, int sb) {
        int tap = idx >> 4;
        size_t off = (size_t)((MODE == 0) ? ((b * 8 + par) * 8 + tap) : (b * 27 + tap)) * 32768
                   + ((size_t)(idx & 15) << 11);
        const float4* src = (const float4*)(W + off);
        float4* dst = (float4*)(&Bs[sb][0][0]);
        cpasync16(dst + t,       src + t);
        cpasync16(dst + t + 256, src + t + 256);
    };

    u64 acc[4][4];
#pragma unroll
    for (int i = 0; i < 4; i++)
#pragma unroll
        for (int j = 0; j < 4; j++) acc[i][j] = 0ULL;

    // ---- prologue ----
    float4 aReg = ld_a(0);
    stage_b(0, 0); asm volatile("cp.async.commit_group;\n");
    stage_b(1, 1); asm volatile("cp.async.commit_group;\n");

    // ---- pipelined mainloop ----
#pragma unroll 1
    for (int idx = 0; idx < NCHUNK; ++idx) {
        const int sa = idx & 1;
        const int sb = idx & 3;
        // STS A(idx) from regs (duplicated into f32x2)
        {
            int kk = kg << 2;
            As[sa][kk + 0][mS] = pk2(aReg.x, aReg.x);
            As[sa][kk + 1][mS] = pk2(aReg.y, aReg.y);
            As[sa][kk + 2][mS] = pk2(aReg.z, aReg.z);
            As[sa][kk + 3][mS] = pk2(aReg.w, aReg.w);
        }
        if (idx + 1 < NCHUNK) aReg = ld_a(idx + 1);
        if (idx + 2 < NCHUNK) stage_b(idx + 2, (idx + 2) & 3);
        asm volatile("cp.async.commit_group;\n");
        asm volatile("cp.async.wait_group 2;\n");
        __syncthreads();

        const u64* Ab = &As[sa][0][0];
        const u64* Bb = &Bs[sb][0][0];
#pragma unroll
        for (int kk = 0; kk < 16; ++kk) {
            ulonglong2 A01 = *(const ulonglong2*)(Ab + kk * 64 + m0);
            ulonglong2 A23 = *(const ulonglong2*)(Ab + kk * 64 + m0 + 2);
            u64 B0 = Bb[kk * 64 + ng];
            u64 B1 = Bb[kk * 64 + ng + 16];
            u64 B2 = Bb[kk * 64 + ng + 32];
            u64 B3 = Bb[kk * 64 + ng + 48];
            ffma2(acc[0][0], A01.x, B0); ffma2(acc[0][1], A01.x, B1);
            ffma2(acc[0][2], A01.x, B2); ffma2(acc[0][3], A01.x, B3);
            ffma2(acc[1][0], A01.y, B0); ffma2(acc[1][1], A01.y, B1);
            ffma2(acc[1][2], A01.y, B2); ffma2(acc[1][3], A01.y, B3);
            ffma2(acc[2][0], A23.x, B0); ffma2(acc[2][1], A23.x, B1);
            ffma2(acc[2][2], A23.x, B2); ffma2(acc[2][3], A23.x, B3);
            ffma2(acc[3][0], A23.y, B0); ffma2(acc[3][1], A23.y, B1);
            ffma2(acc[3][2], A23.y, B2); ffma2(acc[3][3], A23.y, B3);
        }
    }

    // ---- epilogue: raw conv output (norm applied later) ----
#pragma unroll
    for (int i = 0; i < 4; i++) {
        int m = m0 + i;
        int lz = m >> 4, ly = (m >> 2) & 3, lx = m & 3;
        size_t oidx;
        if (MODE == 0) {
            int oz = ((oz0 + lz) << 1) + pd;
            int oy = ((oy0 + ly) << 1) + ph;
            int ox = ((ox0 + lx) << 1) + pw;
            oidx = ((size_t)(((b * 32 + oz) * 32 + oy) * 32 + ox)) * 128;
        } else {
            oidx = ((size_t)(((b * 32 + (oz0 + lz)) * 32 + (oy0 + ly)) * 32 + (ox0 + lx))) * 128;
        }
#pragma unroll
        for (int j = 0; j < 4; j++) {
            float2 v = make_float2(lo32(acc[i][j]), hi32(acc[i][j]));
            *(float2*)(out + oidx + ((size_t)(ng + (j << 4)) << 1)) = v;
        }
    }
}

// ---------------- instance-norm reduction (1024 blocks) ----------------
template <int SRC>  // 0 -> g_y1, 1 -> g_y2
__global__ void reduce_stats_kernel() {
    const float* y = (SRC == 0) ? g_y1 : g_y2;
    int b = blockIdx.x >> 8;
    int chunk = blockIdx.x & 255;       // 128 spatial positions per block
    int c = threadIdx.x & 127;
    int h = threadIdx.x >> 7;           // 0/1: 64 positions each
    const float* p = y + ((size_t)(b * 32768 + chunk * 128 + h * 64)) * 128 + c;
    float s0 = 0.f, q0 = 0.f;
#pragma unroll 4
    for (int i = 0; i < 64; ++i) {
        float v = p[(size_t)i * 128];
        s0 += v; q0 += v * v;
    }
    __shared__ float S[256], Q[256];
    S[threadIdx.x] = s0;
    Q[threadIdx.x] = q0;
    __syncthreads();
    if (h == 0) {
        atomicAdd(&g_sum[b * 128 + c], S[c] + S[c + 128]);
        atomicAdd(&g_sq[b * 128 + c],  Q[c] + Q[c + 128]);
    }
}

// ---------------- fused normalize + relu ----------------
template <int SRC>  // 0: g_y1 -> g_y1 (in place); 1: g_y2 -> dst
__global__ void norm_relu_kernel(float* __restrict__ dst_param) {
    const float* src = (SRC == 0) ? g_y1 : g_y2;
    float* dst       = (SRC == 0) ? g_y1 : dst_param;
    int i4 = blockIdx.x * 256 + threadIdx.x;    // 4,194,304 float4s
    size_t i = (size_t)i4 * 4;
    int c = (int)(i & 127);
    int b = (int)(i >> 22);
    int bc = b * 128 + c;
    float4 v = *(const float4*)(src + i);
    v.x = fmaxf(fmaf(v.x, g_scale[bc],     g_bias[bc]),     0.f);
    v.y = fmaxf(fmaf(v.y, g_scale[bc + 1], g_bias[bc + 1]), 0.f);
    v.z = fmaxf(fmaf(v.z, g_scale[bc + 2], g_bias[bc + 2]), 0.f);
    v.w = fmaxf(fmaf(v.w, g_scale[bc + 3], g_bias[bc + 3]), 0.f);
    *(float4*)(dst + i) = v;
}

// ---------------- launch ----------------
extern "C" void kernel_launch(void* const* d_in, const int* in_sizes, int n_in,
                              void* d_out, int out_size) {
    const float* x    = (const float*)d_in[0];  // [4,16,16,16,256]
    const float* w1   = (const float*)d_in[1];  // [4,3,3,3,256,128]
    const float* w2   = (const float*)d_in[2];  // [4,3,3,3,256,128]
    const float* skip = (const float*)d_in[3];  // [4,32,32,32,128]
    float* out = (float*)d_out;                 // [4,32,32,32,128]
    (void)in_sizes; (void)n_in; (void)out_size;

    // stage 1: upsample+conv1 (parity-collapsed) -> IN -> relu
    zero_stats_kernel<<<1, 512>>>();
    prep_w1e_kernel<<<32768, 256>>>(w1);
    conv_kernel<0><<<2048, 256>>>(x, nullptr);
    reduce_stats_kernel<0><<<1024, 256>>>();
    finalize_stats_kernel<<<1, 512>>>();
    norm_relu_kernel<0><<<16384, 256>>>(nullptr);

    // stage 2: concat(y1n, skip) -> conv2 -> IN -> relu
    zero_stats_kernel<<<1, 512>>>();
    conv_kernel<1><<<2048, 256>>>(skip, w2);
    reduce_stats_kernel<1><<<1024, 256>>>();
    finalize_stats_kernel<<<1, 512>>>();
    norm_relu_kernel<1><<<16384, 256>>>(out);
}